// round 1
// baseline (speedup 1.0000x reference)
#include <cuda_runtime.h>
#include <math.h>

#define NE 4
#define NB 8192
#define NF 2048
#define NL 100
#define NEB (NE*NB)
#define LAM 1.0f

// ---------------- device scratch (no allocations allowed) ----------------
__device__ float  g_sums[NE*NL*NF];   // per-(env,label) feature sums
__device__ float  g_counts[NE*NL];
__device__ float  g_var[NE*NL];
__device__ float  g_visit[NE*NL];
__device__ double g_ce;               // sum over all samples of -logp[y]

// ---------------- zero scratch ----------------
__global__ void zero_kernel() {
    int n = NE*NL*NF;
    for (int i = blockIdx.x*blockDim.x + threadIdx.x; i < n; i += gridDim.x*blockDim.x)
        g_sums[i] = 0.f;
    if (blockIdx.x == 0) {
        if (threadIdx.x < NE*NL) g_counts[threadIdx.x] = 0.f;
        if (threadIdx.x == 0)    g_ce = 0.0;
    }
}

// ---------------- label counts ----------------
__global__ void count_kernel(const int* __restrict__ y) {
    int i = blockIdx.x*blockDim.x + threadIdx.x;
    if (i < NEB) {
        int e = i / NB;
        atomicAdd(&g_counts[e*NL + y[i]], 1.0f);
    }
}

// ---------------- per-(env,label) sums ----------------
// grid: (NF/64, NE, 4)   block: 256 = 4 row-groups x 64 feature-lanes
// dynamic smem: 4 private accumulator copies [4][NL][64] + staged y [2048]
__global__ void sums_kernel(const float* __restrict__ feats,
                            const int*   __restrict__ y) {
    extern __shared__ float sm[];
    float* accs = sm;                          // 4*NL*64 floats = 102400 B
    int*   sy   = (int*)(sm + 4*NL*64);        // 2048 ints = 8192 B

    const int lane  = threadIdx.x & 63;        // feature lane within 64-chunk
    const int g     = threadIdx.x >> 6;        // row group 0..3
    const int fbase = blockIdx.x * 64;
    const int e     = blockIdx.y;
    const int bst   = blockIdx.z * 2048;

    for (int s = threadIdx.x; s < 4*NL*64; s += 256) accs[s] = 0.f;
    for (int s = threadIdx.x; s < 2048;    s += 256) sy[s] = y[e*NB + bst + s];
    __syncthreads();

    const float* fp = feats + ((size_t)e*NB + bst) * NF + fbase + lane;
    float* acc = accs + g*(NL*64) + lane;

    // 512 rows per thread, unrolled by 8 for MLP
    for (int bb = g; bb < 2048; bb += 32) {
        int   yl[8];
        float vv[8];
        #pragma unroll
        for (int u = 0; u < 8; u++) {
            int b = bb + u*4;
            yl[u] = sy[b];
            vv[u] = fp[(size_t)b * NF];
        }
        #pragma unroll
        for (int u = 0; u < 8; u++)
            acc[yl[u]*64] += vv[u];
    }
    __syncthreads();

    for (int s = threadIdx.x; s < NL*64; s += 256) {
        float t = accs[s] + accs[s + NL*64] + accs[s + 2*NL*64] + accs[s + 3*NL*64];
        int l = s >> 6, ff = s & 63;
        atomicAdd(&g_sums[((size_t)e*NL + l)*NF + fbase + ff], t);
    }
}

// ---------------- per-(env,label) variance over features ----------------
__global__ void var_kernel() {
    const int el = blockIdx.x;                 // 0..NE*NL-1
    float cnt = g_counts[el];
    float inv = 1.0f / fmaxf(cnt, 1.0f);
    const float* s = g_sums + (size_t)el * NF;

    float sum = 0.f, sq = 0.f;
    for (int f = threadIdx.x; f < NF; f += 256) {
        float m = s[f] * inv;
        sum += m;
        sq  = fmaf(m, m, sq);
    }
    __shared__ float s1[256], s2[256];
    s1[threadIdx.x] = sum; s2[threadIdx.x] = sq;
    __syncthreads();
    for (int o = 128; o > 0; o >>= 1) {
        if (threadIdx.x < o) { s1[threadIdx.x] += s1[threadIdx.x+o];
                               s2[threadIdx.x] += s2[threadIdx.x+o]; }
        __syncthreads();
    }
    if (threadIdx.x == 0) {
        float S = s1[0], Q = s2[0];
        float mu = S / (float)NF;
        g_var[el]   = (Q - S*mu) / (float)(NF - 1);
        g_visit[el] = (cnt > 0.f) ? 1.f : 0.f;
    }
}

// ---------------- GEMM [32768,2048]x[2048,100] + fused log-softmax CE -----
// block = 256 threads, tile M=128, N padded to 128, K-chunk 32
__global__ void __launch_bounds__(256, 2)
gemm_ce_kernel(const float* __restrict__ feats,
               const int*   __restrict__ y,
               const float* __restrict__ W,
               const float* __restrict__ b) {
    __shared__ float As[128*32];    // feats tile [row][k]
    __shared__ float Ws[32*128];    // W tile [k][col], cols 100..127 zero
    __shared__ float red[8];

    const int tid  = threadIdx.x;
    const int lane = tid & 31;
    const int warp = tid >> 5;
    const int wrow = warp * 16;     // 16 rows per warp
    const int m0   = blockIdx.x * 128;

    float4 acc[16];
    #pragma unroll
    for (int r = 0; r < 16; r++) acc[r] = make_float4(0.f, 0.f, 0.f, 0.f);

    const float4* fv  = (const float4*)feats;

    for (int kt = 0; kt < NF/32; kt++) {
        const int k0 = kt * 32;
        // load A tile: 128 rows x 32 k (as float4)
        #pragma unroll
        for (int i = 0; i < 4; i++) {
            int s = tid + i*256;
            int row = s >> 3, q = s & 7;
            ((float4*)As)[s] = fv[((size_t)(m0 + row))*(NF/4) + (k0 >> 2) + q];
        }
        // load W tile: 32 k x 128 cols (zero-pad cols >= 100)
        #pragma unroll
        for (int i = 0; i < 16; i++) {
            int s = tid + i*256;
            int kr = s >> 7, c = s & 127;
            Ws[s] = (c < NL) ? W[(size_t)(k0 + kr)*NL + c] : 0.f;
        }
        __syncthreads();

        const float4* As4 = (const float4*)As;
        const float4* Ws4 = (const float4*)Ws;
        #pragma unroll
        for (int k4 = 0; k4 < 8; k4++) {
            float4 w0 = Ws4[(k4*4 + 0)*32 + lane];
            float4 w1 = Ws4[(k4*4 + 1)*32 + lane];
            float4 w2 = Ws4[(k4*4 + 2)*32 + lane];
            float4 w3 = Ws4[(k4*4 + 3)*32 + lane];
            #pragma unroll
            for (int r = 0; r < 16; r++) {
                float4 a = As4[(wrow + r)*8 + k4];
                acc[r].x = fmaf(a.x, w0.x, acc[r].x);
                acc[r].y = fmaf(a.x, w0.y, acc[r].y);
                acc[r].z = fmaf(a.x, w0.z, acc[r].z);
                acc[r].w = fmaf(a.x, w0.w, acc[r].w);
                acc[r].x = fmaf(a.y, w1.x, acc[r].x);
                acc[r].y = fmaf(a.y, w1.y, acc[r].y);
                acc[r].z = fmaf(a.y, w1.z, acc[r].z);
                acc[r].w = fmaf(a.y, w1.w, acc[r].w);
                acc[r].x = fmaf(a.z, w2.x, acc[r].x);
                acc[r].y = fmaf(a.z, w2.y, acc[r].y);
                acc[r].z = fmaf(a.z, w2.z, acc[r].z);
                acc[r].w = fmaf(a.z, w2.w, acc[r].w);
                acc[r].x = fmaf(a.w, w3.x, acc[r].x);
                acc[r].y = fmaf(a.w, w3.y, acc[r].y);
                acc[r].z = fmaf(a.w, w3.z, acc[r].z);
                acc[r].w = fmaf(a.w, w3.w, acc[r].w);
            }
        }
        __syncthreads();
    }

    // epilogue: per-row log-softmax CE; lane owns cols 4*lane..4*lane+3
    const int c0 = lane * 4;
    const float NEG = -1e30f;
    float b0 = (c0 + 0 < NL) ? b[c0 + 0] : 0.f;
    float b1 = (c0 + 1 < NL) ? b[c0 + 1] : 0.f;
    float b2 = (c0 + 2 < NL) ? b[c0 + 2] : 0.f;
    float b3 = (c0 + 3 < NL) ? b[c0 + 3] : 0.f;

    float cesum = 0.f;
    #pragma unroll
    for (int r = 0; r < 16; r++) {
        int row = m0 + wrow + r;
        float v0 = (c0 + 0 < NL) ? acc[r].x + b0 : NEG;
        float v1 = (c0 + 1 < NL) ? acc[r].y + b1 : NEG;
        float v2 = (c0 + 2 < NL) ? acc[r].z + b2 : NEG;
        float v3 = (c0 + 3 < NL) ? acc[r].w + b3 : NEG;

        float m = fmaxf(fmaxf(v0, v1), fmaxf(v2, v3));
        #pragma unroll
        for (int o = 16; o > 0; o >>= 1)
            m = fmaxf(m, __shfl_xor_sync(0xffffffffu, m, o));

        float sx = __expf(v0 - m) + __expf(v1 - m) + __expf(v2 - m) + __expf(v3 - m);

        int yr = y[row];
        float own = 0.f;
        if ((yr >> 2) == lane) {
            int j = yr & 3;
            own = (j == 0) ? v0 : (j == 1) ? v1 : (j == 2) ? v2 : v3;
        }
        #pragma unroll
        for (int o = 16; o > 0; o >>= 1) {
            sx  += __shfl_xor_sync(0xffffffffu, sx,  o);
            own += __shfl_xor_sync(0xffffffffu, own, o);
        }
        cesum += m + __logf(sx) - own;
    }
    if (lane == 0) red[warp] = cesum;
    __syncthreads();
    if (tid == 0) {
        float t = 0.f;
        #pragma unroll
        for (int w = 0; w < 8; w++) t += red[w];
        atomicAdd(&g_ce, (double)t);
    }
}

// ---------------- label aggregation + final output ----------------
__global__ void combine_kernel(float* __restrict__ out) {
    const int tid = threadIdx.x;
    float pl_sel = 0.f, sel = 0.f;
    if (tid < NL) {
        float nvis = 0.f, vv = 0.f;
        #pragma unroll
        for (int e = 0; e < NE; e++) {
            float vis = g_visit[e*NL + tid];
            nvis += vis;
            vv   += g_var[e*NL + tid] * vis;
        }
        float per = vv / fmaxf(nvis, 1.0f);
        sel    = (nvis > 1.5f) ? 1.f : 0.f;
        pl_sel = per * sel;
    }
    __shared__ float s1[128], s2[128];
    s1[tid] = pl_sel; s2[tid] = sel;
    __syncthreads();
    for (int o = 64; o > 0; o >>= 1) {
        if (tid < o) { s1[tid] += s1[tid+o]; s2[tid] += s2[tid+o]; }
        __syncthreads();
    }
    if (tid == 0) {
        float mean_loss = LAM * s1[0] / fmaxf(s2[0], 1.0f);
        out[0] = mean_loss + (float)(g_ce / (double)NEB);
    }
}

// ---------------- launch ----------------
extern "C" void kernel_launch(void* const* d_in, const int* in_sizes, int n_in,
                              void* d_out, int out_size) {
    const float* feats = (const float*)d_in[0];
    const int*   y     = (const int*)  d_in[1];
    const float* W     = (const float*)d_in[2];
    const float* b     = (const float*)d_in[3];
    float* out = (float*)d_out;

    const int sums_smem = 4*NL*64*(int)sizeof(float) + 2048*(int)sizeof(int); // 110592
    cudaFuncSetAttribute(sums_kernel, cudaFuncAttributeMaxDynamicSharedMemorySize, sums_smem);

    zero_kernel  <<<256, 256>>>();
    count_kernel <<<(NEB + 255)/256, 256>>>(y);
    sums_kernel  <<<dim3(NF/64, NE, 4), 256, sums_smem>>>(feats, y);
    gemm_ce_kernel<<<NEB/128, 256>>>(feats, y, W, b);
    var_kernel   <<<NE*NL, 256>>>();
    combine_kernel<<<1, 128>>>(out);
}

// round 3
// speedup vs baseline: 2.5821x; 2.5821x over previous
#include <cuda_runtime.h>
#include <cuda_bf16.h>
#include <math.h>
#include <stdint.h>

#define NE 4
#define NB 8192
#define NF 2048
#define NL 100
#define NEB (NE*NB)
#define LAM 1.0f

// ---------------- device scratch (no allocations allowed) ----------------
__device__ float  g_sums[NE*NL*NF];
__device__ float  g_counts[NE*NL];
__device__ float  g_var[NE*NL];
__device__ float  g_visit[NE*NL];
__device__ double g_ce;
__device__ __align__(16) __nv_bfloat16 g_Wb[128*NF];       // W^T bf16 [n][k], n>=100 zero
__device__ __align__(16) __nv_bfloat16 g_featsb[(size_t)NEB*NF]; // feats bf16

// ======================= PTX helpers (sm_80-compatible) ==================
__device__ __forceinline__ uint32_t smem_u32(const void* p) {
    return (uint32_t)__cvta_generic_to_shared(p);
}
__device__ __forceinline__ uint32_t swz128(uint32_t off) {
    return off ^ ((off >> 3) & 0x70u);
}
__device__ __forceinline__ void cp16(uint32_t dst, const void* src) {
    asm volatile("cp.async.cg.shared.global [%0], [%1], 16;" :: "r"(dst), "l"(src));
}
__device__ __forceinline__ void cp_commit() {
    asm volatile("cp.async.commit_group;" ::: "memory");
}
__device__ __forceinline__ void cp_wait1() {
    asm volatile("cp.async.wait_group 1;" ::: "memory");
}
__device__ __forceinline__ void cp_wait0() {
    asm volatile("cp.async.wait_group 0;" ::: "memory");
}
__device__ __forceinline__ void ldm_x4(uint32_t* r, uint32_t a) {
    asm volatile("ldmatrix.sync.aligned.m8n8.x4.shared.b16 {%0,%1,%2,%3}, [%4];"
                 : "=r"(r[0]), "=r"(r[1]), "=r"(r[2]), "=r"(r[3]) : "r"(a));
}
__device__ __forceinline__ void ldm_x2(uint32_t* r, uint32_t a) {
    asm volatile("ldmatrix.sync.aligned.m8n8.x2.shared.b16 {%0,%1}, [%2];"
                 : "=r"(r[0]), "=r"(r[1]) : "r"(a));
}
__device__ __forceinline__ void mma16816(float* c, const uint32_t* a, const uint32_t* b) {
    asm volatile(
        "mma.sync.aligned.m16n8k16.row.col.f32.bf16.bf16.f32 "
        "{%0,%1,%2,%3}, {%4,%5,%6,%7}, {%8,%9}, {%0,%1,%2,%3};"
        : "+f"(c[0]), "+f"(c[1]), "+f"(c[2]), "+f"(c[3])
        : "r"(a[0]), "r"(a[1]), "r"(a[2]), "r"(a[3]), "r"(b[0]), "r"(b[1]));
}

// ---------------- zero scratch ----------------
__global__ void zero_kernel() {
    int n = NE*NL*NF;
    for (int i = blockIdx.x*blockDim.x + threadIdx.x; i < n; i += gridDim.x*blockDim.x)
        g_sums[i] = 0.f;
    if (blockIdx.x == 0) {
        if (threadIdx.x < NE*NL) g_counts[threadIdx.x] = 0.f;
        if (threadIdx.x == 0)    g_ce = 0.0;
    }
}

// ---------------- prep W^T bf16, zero-padded to 128 rows ----------------
__global__ void prep_wb_kernel(const float* __restrict__ W) {
    int i = blockIdx.x*blockDim.x + threadIdx.x;
    if (i < 128*NF) {
        int n = i >> 11;
        int k = i & (NF-1);
        float v = (n < NL) ? W[(size_t)k*NL + n] : 0.f;
        g_Wb[i] = __float2bfloat16(v);
    }
}

// ---------------- label counts ----------------
__global__ void count_kernel(const int* __restrict__ y) {
    int i = blockIdx.x*blockDim.x + threadIdx.x;
    if (i < NEB) {
        int e = i / NB;
        atomicAdd(&g_counts[e*NL + y[i]], 1.0f);
    }
}

// ---------------- per-(env,label) sums + feats bf16 conversion ----------
__global__ void sums_kernel(const float* __restrict__ feats,
                            const int*   __restrict__ y) {
    extern __shared__ float sm[];
    float* accs = sm;                          // 4*NL*64 floats
    int*   sy   = (int*)(sm + 4*NL*64);        // 2048 ints

    const int lane  = threadIdx.x & 63;
    const int g     = threadIdx.x >> 6;
    const int fbase = blockIdx.x * 64;
    const int e     = blockIdx.y;
    const int bst   = blockIdx.z * 2048;

    for (int s = threadIdx.x; s < 4*NL*64; s += 256) accs[s] = 0.f;
    for (int s = threadIdx.x; s < 2048;    s += 256) sy[s] = y[e*NB + bst + s];
    __syncthreads();

    const float* fp = feats + ((size_t)e*NB + bst) * NF + fbase + lane;
    __nv_bfloat16* op = g_featsb + ((size_t)e*NB + bst) * NF + fbase + lane;
    float* acc = accs + g*(NL*64) + lane;

    for (int bb = g; bb < 2048; bb += 32) {
        int   yl[8];
        float vv[8];
        #pragma unroll
        for (int u = 0; u < 8; u++) {
            int bq = bb + u*4;
            yl[u] = sy[bq];
            vv[u] = fp[(size_t)bq * NF];
        }
        #pragma unroll
        for (int u = 0; u < 8; u++) {
            int bq = bb + u*4;
            op[(size_t)bq * NF] = __float2bfloat16(vv[u]);
            acc[yl[u]*64] += vv[u];
        }
    }
    __syncthreads();

    for (int s = threadIdx.x; s < NL*64; s += 256) {
        float t = accs[s] + accs[s + NL*64] + accs[s + 2*NL*64] + accs[s + 3*NL*64];
        int l = s >> 6, ff = s & 63;
        atomicAdd(&g_sums[((size_t)e*NL + l)*NF + fbase + ff], t);
    }
}

// ---------------- per-(env,label) variance over features ----------------
__global__ void var_kernel() {
    const int el = blockIdx.x;
    float cnt = g_counts[el];
    float inv = 1.0f / fmaxf(cnt, 1.0f);
    const float* s = g_sums + (size_t)el * NF;

    float sum = 0.f, sq = 0.f;
    for (int f = threadIdx.x; f < NF; f += 256) {
        float m = s[f] * inv;
        sum += m;
        sq  = fmaf(m, m, sq);
    }
    __shared__ float s1[256], s2[256];
    s1[threadIdx.x] = sum; s2[threadIdx.x] = sq;
    __syncthreads();
    for (int o = 128; o > 0; o >>= 1) {
        if (threadIdx.x < o) { s1[threadIdx.x] += s1[threadIdx.x+o];
                               s2[threadIdx.x] += s2[threadIdx.x+o]; }
        __syncthreads();
    }
    if (threadIdx.x == 0) {
        float S = s1[0], Q = s2[0];
        float mu = S / (float)NF;
        g_var[el]   = (Q - S*mu) / (float)(NF - 1);
        g_visit[el] = (cnt > 0.f) ? 1.f : 0.f;
    }
}

// ========== HMMA GEMM [32768,2048]x[2048,128pad] + fused CE =============
// grid = 256, block = 256 (8 warps: 4 M-bands x 2 N-halves)
// Dynamic smem: 1KB align pad + A0/A1/B0/B1, each 128x64 bf16 swizzled (16KB)
#define NCHUNK (NF/64)   // 32
#define GSM_SIZE (1024 + 4*16384)

__global__ void __launch_bounds__(256, 2)
gemm_ce_tc_kernel(const int* __restrict__ y, const float* __restrict__ b) {
    extern __shared__ char smx[];
    const uint32_t tile0 = (smem_u32(smx) + 1023u) & ~1023u;
    const uint32_t tA[2] = { tile0,          tile0 + 16384 };
    const uint32_t tB[2] = { tile0 + 32768,  tile0 + 49152 };

    __shared__ float bias_s[128];
    __shared__ float smax2[2][128];
    __shared__ float sown[2][128];
    __shared__ float sexp[2][128];
    __shared__ float redw[8];

    const int tid  = threadIdx.x;
    const int wid  = tid >> 5;
    const int lane = tid & 31;
    const int wm   = wid >> 1;      // 0..3 (M band of 32 rows)
    const int wn   = wid & 1;       // 0..1 (N half of 64 cols)
    const int m0   = blockIdx.x * 128;
    const int lq   = lane & 3;
    const int lr4  = lane >> 2;

    if (tid < 128) bias_s[tid] = (tid < NL) ? b[tid] : 0.f;

    float acc[2][8][4];
    #pragma unroll
    for (int mt = 0; mt < 2; mt++)
        #pragma unroll
        for (int nt = 0; nt < 8; nt++)
            #pragma unroll
            for (int j = 0; j < 4; j++) acc[mt][nt][j] = 0.f;

    // ---- async copy of one K-chunk into stage st ----
    auto issue = [&](int kt, int st) {
        #pragma unroll
        for (int i = 0; i < 4; i++) {
            int idx = i*256 + tid;           // 0..1023
            int row = idx >> 3, q = idx & 7;
            cp16(tA[st] + swz128((uint32_t)(row*128 + q*16)),
                 g_featsb + (size_t)(m0 + row)*NF + kt*64 + q*8);
        }
        #pragma unroll
        for (int i = 0; i < 4; i++) {
            int idx = i*256 + tid;
            int n = idx >> 3, q = idx & 7;
            cp16(tB[st] + swz128((uint32_t)(n*128 + q*16)),
                 g_Wb + (size_t)n*NF + kt*64 + q*8);
        }
        cp_commit();
    };

    issue(0, 0);

    for (int kt = 0; kt < NCHUNK; kt++) {
        const int s = kt & 1;
        if (kt + 1 < NCHUNK) { issue(kt + 1, s ^ 1); cp_wait1(); }
        else                 { cp_wait0(); }
        __syncthreads();

        #pragma unroll
        for (int k16 = 0; k16 < 4; k16++) {
            // B fragments: 8 n-tiles of this warp's N half
            uint32_t bf[8][2];
            {
                int l = lane & 15;
                uint32_t boff = (uint32_t)(k16*32 + (l >> 3)*16);
                #pragma unroll
                for (int nt = 0; nt < 8; nt++) {
                    int n0 = wn*64 + nt*8;
                    ldm_x2(bf[nt], tB[s] + swz128((uint32_t)((n0 + (l & 7))*128) + boff));
                }
            }
            #pragma unroll
            for (int mt = 0; mt < 2; mt++) {
                uint32_t af[4];
                uint32_t aoff = (uint32_t)(k16*32 + (lane >> 4)*16);
                ldm_x4(af, tA[s] + swz128((uint32_t)((wm*32 + mt*16 + (lane & 15))*128) + aoff));
                #pragma unroll
                for (int nt = 0; nt < 8; nt++)
                    mma16816(acc[mt][nt], af, bf[nt]);
            }
        }
        __syncthreads();
    }

    // ---------------- fused CE epilogue ----------------
    // Phase A: per-row max + own-label value (quad reduce, store per N-half)
    #pragma unroll
    for (int mt = 0; mt < 2; mt++) {
        #pragma unroll
        for (int h = 0; h < 2; h++) {
            int lrow = wm*32 + mt*16 + h*8 + lr4;
            int yv = y[m0 + lrow];
            float mx = -1e30f, own = 0.f;
            #pragma unroll
            for (int nt = 0; nt < 8; nt++) {
                #pragma unroll
                for (int j = 0; j < 2; j++) {
                    int gc = wn*64 + nt*8 + 2*lq + j;
                    float v = acc[mt][nt][h*2 + j] + bias_s[gc];
                    if (gc >= NL) v = -1e30f;
                    mx = fmaxf(mx, v);
                    if (gc == yv) own = v;
                }
            }
            mx = fmaxf(mx, __shfl_xor_sync(0xffffffffu, mx, 1));
            mx = fmaxf(mx, __shfl_xor_sync(0xffffffffu, mx, 2));
            own += __shfl_xor_sync(0xffffffffu, own, 1);
            own += __shfl_xor_sync(0xffffffffu, own, 2);
            if (lq == 0) { smax2[wn][lrow] = mx; sown[wn][lrow] = own; }
        }
    }
    __syncthreads();

    // Phase B: expsum with combined max
    #pragma unroll
    for (int mt = 0; mt < 2; mt++) {
        #pragma unroll
        for (int h = 0; h < 2; h++) {
            int lrow = wm*32 + mt*16 + h*8 + lr4;
            float mxc = fmaxf(smax2[0][lrow], smax2[1][lrow]);
            float se = 0.f;
            #pragma unroll
            for (int nt = 0; nt < 8; nt++) {
                #pragma unroll
                for (int j = 0; j < 2; j++) {
                    int gc = wn*64 + nt*8 + 2*lq + j;
                    float v = acc[mt][nt][h*2 + j] + bias_s[gc];
                    if (gc < NL) se += __expf(v - mxc);
                }
            }
            se += __shfl_xor_sync(0xffffffffu, se, 1);
            se += __shfl_xor_sync(0xffffffffu, se, 2);
            if (lq == 0) sexp[wn][lrow] = se;
        }
    }
    __syncthreads();

    // Final: one thread per row
    float ce = 0.f;
    if (tid < 128) {
        float mxc = fmaxf(smax2[0][tid], smax2[1][tid]);
        float se  = sexp[0][tid] + sexp[1][tid];
        float own = sown[0][tid] + sown[1][tid];
        ce = mxc + __logf(se) - own;
    }
    #pragma unroll
    for (int o = 16; o > 0; o >>= 1)
        ce += __shfl_xor_sync(0xffffffffu, ce, o);
    if (lane == 0) redw[wid] = ce;
    __syncthreads();
    if (tid == 0) {
        float t = redw[0] + redw[1] + redw[2] + redw[3];
        atomicAdd(&g_ce, (double)t);
    }
}

// ---------------- label aggregation + final output ----------------
__global__ void combine_kernel(float* __restrict__ out) {
    const int tid = threadIdx.x;
    float pl_sel = 0.f, sel = 0.f;
    if (tid < NL) {
        float nvis = 0.f, vv = 0.f;
        #pragma unroll
        for (int e = 0; e < NE; e++) {
            float vis = g_visit[e*NL + tid];
            nvis += vis;
            vv   += g_var[e*NL + tid] * vis;
        }
        float per = vv / fmaxf(nvis, 1.0f);
        sel    = (nvis > 1.5f) ? 1.f : 0.f;
        pl_sel = per * sel;
    }
    __shared__ float s1[128], s2[128];
    s1[tid] = pl_sel; s2[tid] = sel;
    __syncthreads();
    for (int o = 64; o > 0; o >>= 1) {
        if (tid < o) { s1[tid] += s1[tid+o]; s2[tid] += s2[tid+o]; }
        __syncthreads();
    }
    if (tid == 0) {
        float mean_loss = LAM * s1[0] / fmaxf(s2[0], 1.0f);
        out[0] = mean_loss + (float)(g_ce / (double)NEB);
    }
}

// ---------------- launch ----------------
extern "C" void kernel_launch(void* const* d_in, const int* in_sizes, int n_in,
                              void* d_out, int out_size) {
    const float* feats = (const float*)d_in[0];
    const int*   y     = (const int*)  d_in[1];
    const float* W     = (const float*)d_in[2];
    const float* b     = (const float*)d_in[3];
    float* out = (float*)d_out;

    const int sums_smem = 4*NL*64*(int)sizeof(float) + 2048*(int)sizeof(int);
    cudaFuncSetAttribute(sums_kernel, cudaFuncAttributeMaxDynamicSharedMemorySize, sums_smem);
    cudaFuncSetAttribute(gemm_ce_tc_kernel, cudaFuncAttributeMaxDynamicSharedMemorySize, GSM_SIZE);

    zero_kernel   <<<256, 256>>>();
    prep_wb_kernel<<<(128*NF + 255)/256, 256>>>(W);
    count_kernel  <<<(NEB + 255)/256, 256>>>(y);
    sums_kernel   <<<dim3(NF/64, NE, 4), 256, sums_smem>>>(feats, y);
    gemm_ce_tc_kernel<<<NEB/128, 256, GSM_SIZE>>>(y, b);
    var_kernel    <<<NE*NL, 256>>>();
    combine_kernel<<<1, 128>>>(out);
}

// round 4
// speedup vs baseline: 2.9159x; 1.1293x over previous
#include <cuda_runtime.h>
#include <cuda_bf16.h>
#include <math.h>
#include <stdint.h>

#define NE 4
#define NB 8192
#define NF 2048
#define NL 100
#define NEB (NE*NB)
#define LAM 1.0f

// ---------------- device scratch (no allocations allowed) ----------------
__device__ float  g_sums[NE*NL*NF];
__device__ float  g_counts[NE*NL];
__device__ float  g_var[NE*NL];
__device__ float  g_visit[NE*NL];
__device__ double g_ce;
__device__ __align__(16) __nv_bfloat16 g_Wb[128*NF];   // W^T bf16 [n][k], n>=100 zero

// ======================= PTX helpers (sm_80-compatible) ==================
__device__ __forceinline__ uint32_t smem_u32(const void* p) {
    return (uint32_t)__cvta_generic_to_shared(p);
}
__device__ __forceinline__ uint32_t swz128(uint32_t off) {   // 128B-row swizzle
    return off ^ ((off >> 3) & 0x70u);
}
__device__ __forceinline__ uint32_t swz256(uint32_t off) {   // 256B-row swizzle
    return off ^ ((off >> 4) & 0xF0u);
}
__device__ __forceinline__ void cp16(uint32_t dst, const void* src) {
    asm volatile("cp.async.cg.shared.global [%0], [%1], 16;" :: "r"(dst), "l"(src));
}
__device__ __forceinline__ void cp_commit() {
    asm volatile("cp.async.commit_group;" ::: "memory");
}
__device__ __forceinline__ void cp_wait1() {
    asm volatile("cp.async.wait_group 1;" ::: "memory");
}
__device__ __forceinline__ void cp_wait0() {
    asm volatile("cp.async.wait_group 0;" ::: "memory");
}
__device__ __forceinline__ void ldm_x4(uint32_t* r, uint32_t a) {
    asm volatile("ldmatrix.sync.aligned.m8n8.x4.shared.b16 {%0,%1,%2,%3}, [%4];"
                 : "=r"(r[0]), "=r"(r[1]), "=r"(r[2]), "=r"(r[3]) : "r"(a));
}
__device__ __forceinline__ void ldm_x2(uint32_t* r, uint32_t a) {
    asm volatile("ldmatrix.sync.aligned.m8n8.x2.shared.b16 {%0,%1}, [%2];"
                 : "=r"(r[0]), "=r"(r[1]) : "r"(a));
}
__device__ __forceinline__ void ldm_x2t(uint32_t* r, uint32_t a) {
    asm volatile("ldmatrix.sync.aligned.m8n8.x2.trans.shared.b16 {%0,%1}, [%2];"
                 : "=r"(r[0]), "=r"(r[1]) : "r"(a));
}
__device__ __forceinline__ void mma16816(float* c, const uint32_t* a, const uint32_t* b) {
    asm volatile(
        "mma.sync.aligned.m16n8k16.row.col.f32.bf16.bf16.f32 "
        "{%0,%1,%2,%3}, {%4,%5,%6,%7}, {%8,%9}, {%0,%1,%2,%3};"
        : "+f"(c[0]), "+f"(c[1]), "+f"(c[2]), "+f"(c[3])
        : "r"(a[0]), "r"(a[1]), "r"(a[2]), "r"(a[3]), "r"(b[0]), "r"(b[1]));
}
__device__ __forceinline__ uint2 cvt_f4_bf16x4(float4 v) {
    __nv_bfloat162 lo = __float22bfloat162_rn(make_float2(v.x, v.y));
    __nv_bfloat162 hi = __float22bfloat162_rn(make_float2(v.z, v.w));
    return make_uint2(*(uint32_t*)&lo, *(uint32_t*)&hi);
}

// ---------------- zero scratch ----------------
__global__ void zero_kernel() {
    int n = NE*NL*NF;
    for (int i = blockIdx.x*blockDim.x + threadIdx.x; i < n; i += gridDim.x*blockDim.x)
        g_sums[i] = 0.f;
    if (blockIdx.x == 0) {
        if (threadIdx.x < NE*NL) g_counts[threadIdx.x] = 0.f;
        if (threadIdx.x == 0)    g_ce = 0.0;
    }
}

// ---------------- prep W^T bf16, zero-padded to 128 rows ----------------
__global__ void prep_wb_kernel(const float* __restrict__ W) {
    int i = blockIdx.x*blockDim.x + threadIdx.x;
    if (i < 128*NF) {
        int n = i >> 11;
        int k = i & (NF-1);
        float v = (n < NL) ? W[(size_t)k*NL + n] : 0.f;
        g_Wb[i] = __float2bfloat16(v);
    }
}

// ---------------- label counts ----------------
__global__ void count_kernel(const int* __restrict__ y) {
    int i = blockIdx.x*blockDim.x + threadIdx.x;
    if (i < NEB) {
        int e = i / NB;
        atomicAdd(&g_counts[e*NL + y[i]], 1.0f);
    }
}

// ---------------- per-(env,label) variance over features ----------------
__global__ void var_kernel() {
    const int el = blockIdx.x;
    float cnt = g_counts[el];
    float inv = 1.0f / fmaxf(cnt, 1.0f);
    const float* s = g_sums + (size_t)el * NF;

    float sum = 0.f, sq = 0.f;
    for (int f = threadIdx.x; f < NF; f += 256) {
        float m = s[f] * inv;
        sum += m;
        sq  = fmaf(m, m, sq);
    }
    __shared__ float s1[256], s2[256];
    s1[threadIdx.x] = sum; s2[threadIdx.x] = sq;
    __syncthreads();
    for (int o = 128; o > 0; o >>= 1) {
        if (threadIdx.x < o) { s1[threadIdx.x] += s1[threadIdx.x+o];
                               s2[threadIdx.x] += s2[threadIdx.x+o]; }
        __syncthreads();
    }
    if (threadIdx.x == 0) {
        float S = s1[0], Q = s2[0];
        float mu = S / (float)NF;
        g_var[el]   = (Q - S*mu) / (float)(NF - 1);
        g_visit[el] = (cnt > 0.f) ? 1.f : 0.f;
    }
}

// ========== HMMA GEMM [32768,2048]x[2048,128pad] + fused CE =============
// grid = 256, block = 256 (8 warps: 4 M-bands x 2 N-halves)
// feats read fp32, converted to bf16 in registers, STS into 2-stage A smem.
// W read via cp.async, 3-stage B smem.
#define NCHUNK (NF/64)   // 32
#define CE_SMEM (1024 + 2*16384 + 3*16384)  // 82944

__global__ void __launch_bounds__(256, 2)
gemm_ce_tc_kernel(const float* __restrict__ feats,
                  const int*   __restrict__ y,
                  const float* __restrict__ b) {
    extern __shared__ char smx[];
    const uint32_t tile0 = (smem_u32(smx) + 1023u) & ~1023u;
    const uint32_t tA[2] = { tile0, tile0 + 16384 };
    const uint32_t tB[3] = { tile0 + 32768, tile0 + 49152, tile0 + 65536 };

    __shared__ float bias_s[128];
    __shared__ float smax2[2][128];
    __shared__ float sown[2][128];
    __shared__ float sexp[2][128];
    __shared__ float redw[8];

    const int tid  = threadIdx.x;
    const int wid  = tid >> 5;
    const int lane = tid & 31;
    const int wm   = wid >> 1;
    const int wn   = wid & 1;
    const int m0   = blockIdx.x * 128;
    const int lq   = lane & 3;
    const int lr4  = lane >> 2;

    if (tid < 128) bias_s[tid] = (tid < NL) ? b[tid] : 0.f;

    float acc[2][8][4];
    #pragma unroll
    for (int mt = 0; mt < 2; mt++)
        #pragma unroll
        for (int nt = 0; nt < 8; nt++)
            #pragma unroll
            for (int j = 0; j < 4; j++) acc[mt][nt][j] = 0.f;

    const float4* fv = (const float4*)feats;
    uint2 st[8];

    auto load_regs = [&](int kt) {
        #pragma unroll
        for (int i = 0; i < 8; i++) {
            int idx = i*256 + tid;          // 0..2047
            int row = idx >> 4, q = idx & 15;
            st[i] = cvt_f4_bf16x4(fv[(size_t)(m0 + row)*(NF/4) + kt*16 + q]);
        }
    };
    auto sts_regs = [&](int s) {
        #pragma unroll
        for (int i = 0; i < 8; i++) {
            int idx = i*256 + tid;
            int row = idx >> 4, q = idx & 15;
            asm volatile("st.shared.v2.u32 [%0], {%1, %2};"
                         :: "r"(tA[s] + swz128((uint32_t)(row*128 + q*8))),
                            "r"(st[i].x), "r"(st[i].y) : "memory");
        }
    };
    auto issueB = [&](int kt, int stg) {
        #pragma unroll
        for (int i = 0; i < 4; i++) {
            int idx = i*256 + tid;          // 0..1023
            int n = idx >> 3, q = idx & 7;
            cp16(tB[stg] + swz128((uint32_t)(n*128 + q*16)),
                 g_Wb + (size_t)n*NF + kt*64 + q*8);
        }
        cp_commit();
    };

    load_regs(0);
    issueB(0, 0);
    issueB(1, 1);

    for (int kt = 0; kt < NCHUNK; kt++) {
        const int sa = kt & 1;
        const int sb = kt % 3;
        sts_regs(sa);
        if (kt + 1 < NCHUNK) load_regs(kt + 1);
        if (kt + 1 < NCHUNK) cp_wait1(); else cp_wait0();
        __syncthreads();
        if (kt + 2 < NCHUNK) issueB(kt + 2, (kt + 2) % 3);

        #pragma unroll
        for (int k16 = 0; k16 < 4; k16++) {
            uint32_t bf[8][2];
            {
                int l = lane & 15;
                uint32_t boff = (uint32_t)(k16*32 + (l >> 3)*16);
                #pragma unroll
                for (int nt = 0; nt < 8; nt++) {
                    int n0 = wn*64 + nt*8;
                    ldm_x2(bf[nt], tB[sb] + swz128((uint32_t)((n0 + (l & 7))*128) + boff));
                }
            }
            #pragma unroll
            for (int mt = 0; mt < 2; mt++) {
                uint32_t af[4];
                uint32_t aoff = (uint32_t)(k16*32 + (lane >> 4)*16);
                ldm_x4(af, tA[sa] + swz128((uint32_t)((wm*32 + mt*16 + (lane & 15))*128) + aoff));
                #pragma unroll
                for (int nt = 0; nt < 8; nt++)
                    mma16816(acc[mt][nt], af, bf[nt]);
            }
        }
    }
    __syncthreads();

    // ---------------- fused CE epilogue ----------------
    #pragma unroll
    for (int mt = 0; mt < 2; mt++) {
        #pragma unroll
        for (int h = 0; h < 2; h++) {
            int lrow = wm*32 + mt*16 + h*8 + lr4;
            int yv = y[m0 + lrow];
            float mx = -1e30f, own = 0.f;
            #pragma unroll
            for (int nt = 0; nt < 8; nt++) {
                #pragma unroll
                for (int j = 0; j < 2; j++) {
                    int gc = wn*64 + nt*8 + 2*lq + j;
                    float v = acc[mt][nt][h*2 + j] + bias_s[gc];
                    if (gc >= NL) v = -1e30f;
                    mx = fmaxf(mx, v);
                    if (gc == yv) own = v;
                }
            }
            mx = fmaxf(mx, __shfl_xor_sync(0xffffffffu, mx, 1));
            mx = fmaxf(mx, __shfl_xor_sync(0xffffffffu, mx, 2));
            own += __shfl_xor_sync(0xffffffffu, own, 1);
            own += __shfl_xor_sync(0xffffffffu, own, 2);
            if (lq == 0) { smax2[wn][lrow] = mx; sown[wn][lrow] = own; }
        }
    }
    __syncthreads();

    #pragma unroll
    for (int mt = 0; mt < 2; mt++) {
        #pragma unroll
        for (int h = 0; h < 2; h++) {
            int lrow = wm*32 + mt*16 + h*8 + lr4;
            float mxc = fmaxf(smax2[0][lrow], smax2[1][lrow]);
            float se = 0.f;
            #pragma unroll
            for (int nt = 0; nt < 8; nt++) {
                #pragma unroll
                for (int j = 0; j < 2; j++) {
                    int gc = wn*64 + nt*8 + 2*lq + j;
                    float v = acc[mt][nt][h*2 + j] + bias_s[gc];
                    if (gc < NL) se += __expf(v - mxc);
                }
            }
            se += __shfl_xor_sync(0xffffffffu, se, 1);
            se += __shfl_xor_sync(0xffffffffu, se, 2);
            if (lq == 0) sexp[wn][lrow] = se;
        }
    }
    __syncthreads();

    float ce = 0.f;
    if (tid < 128) {
        float mxc = fmaxf(smax2[0][tid], smax2[1][tid]);
        float se  = sexp[0][tid] + sexp[1][tid];
        float own = sown[0][tid] + sown[1][tid];
        ce = mxc + __logf(se) - own;
    }
    #pragma unroll
    for (int o = 16; o > 0; o >>= 1)
        ce += __shfl_xor_sync(0xffffffffu, ce, o);
    if (lane == 0) redw[wid] = ce;
    __syncthreads();
    if (tid == 0) {
        float t = redw[0] + redw[1] + redw[2] + redw[3];
        atomicAdd(&g_ce, (double)t);
    }
}

// ======= sums GEMM: sums[e] = onehot(y[e])^T [L,B] @ feats[e] [B,F] ======
// grid = (16 F-chunks, NE, 4 K-splits), block 256 (8 warps: 4 Lband x 2 Fhalf)
// M=128 labels (pad), N=128 F, K=2048 batch per CTA (32 chunks of 64).
// A (onehot) built in registers via __vcmpeq2 on packed y-pairs.
// B (feats) fp32->bf16 reg-staged into 256B-row swizzled smem, ldmatrix.trans.
#define SCHUNK 32
#define SU_SMEM (1024 + 2*16384 + 4096)   // 37888
#define ONE2 0x3F803F80u

__global__ void __launch_bounds__(256, 2)
sums_gemm_kernel(const float* __restrict__ feats, const int* __restrict__ y) {
    extern __shared__ char smx[];
    const uint32_t tile0 = (smem_u32(smx) + 1023u) & ~1023u;
    const uint32_t tF[2] = { tile0, tile0 + 16384 };
    uint32_t* sy16 = (uint32_t*)(smx + (tile0 - smem_u32(smx)) + 32768);

    const int tid  = threadIdx.x;
    const int wid  = tid >> 5;
    const int lane = tid & 31;
    const int wm   = wid >> 1;      // label band (32 labels)
    const int wn   = wid & 1;       // F half (64 cols)
    const int n0   = blockIdx.x * 128;
    const int e    = blockIdx.y;
    const int bz   = blockIdx.z * 2048;
    const int lq   = lane & 3;
    const int lr4  = lane >> 2;

    // pack y pairs for this CTA's batch range: sy16[j] = y[2j] | y[2j+1]<<16
    {
        const int* yp = y + e*NB + bz;
        for (int j = tid; j < 1024; j += 256)
            sy16[j] = (uint32_t)yp[2*j] | ((uint32_t)yp[2*j + 1] << 16);
    }

    float acc[2][8][4];
    #pragma unroll
    for (int mt = 0; mt < 2; mt++)
        #pragma unroll
        for (int nt = 0; nt < 8; nt++)
            #pragma unroll
            for (int j = 0; j < 4; j++) acc[mt][nt][j] = 0.f;

    const float4* fv = (const float4*)feats;
    uint2 st[8];

    auto load_regs = [&](int kt) {
        #pragma unroll
        for (int i = 0; i < 8; i++) {
            int idx = i*256 + tid;          // 0..2047
            int row = idx >> 5, q = idx & 31;   // 64 batch rows x 32 float4
            st[i] = cvt_f4_bf16x4(
                fv[(size_t)(e*NB + bz + kt*64 + row)*(NF/4) + (n0 >> 2) + q]);
        }
    };
    auto sts_regs = [&](int s) {
        #pragma unroll
        for (int i = 0; i < 8; i++) {
            int idx = i*256 + tid;
            int row = idx >> 5, q = idx & 31;
            asm volatile("st.shared.v2.u32 [%0], {%1, %2};"
                         :: "r"(tF[s] + swz256((uint32_t)(row*256 + q*8))),
                            "r"(st[i].x), "r"(st[i].y) : "memory");
        }
    };

    load_regs(0);

    for (int kt = 0; kt < SCHUNK; kt++) {
        const int s = kt & 1;
        sts_regs(s);
        if (kt + 1 < SCHUNK) load_regs(kt + 1);
        __syncthreads();

        #pragma unroll
        for (int k16 = 0; k16 < 4; k16++) {
            // B fragments: feats [batch K x F N] row-major, ldmatrix.trans
            uint32_t bf[8][2];
            {
                int rr = k16*16 + (lane & 15);   // batch row within chunk
                #pragma unroll
                for (int nt = 0; nt < 8; nt++) {
                    uint32_t cn = (uint32_t)(wn*8 + nt);   // 16B chunk index (8 F cols)
                    ldm_x2t(bf[nt], tF[s] + swz256((uint32_t)(rr*256) + cn*16));
                }
            }
            // A fragments: onehot, in registers
            uint32_t yp0 = sy16[kt*32 + k16*8 + lq];
            uint32_t yp1 = sy16[kt*32 + k16*8 + 4 + lq];
            #pragma unroll
            for (int mt = 0; mt < 2; mt++) {
                int lm = wm*32 + mt*16 + lr4;
                uint32_t ll  = (uint32_t)lm | ((uint32_t)lm << 16);
                uint32_t ll8 = ll + 0x00080008u;
                uint32_t af[4];
                af[0] = __vcmpeq2(yp0, ll)  & ONE2;
                af[1] = __vcmpeq2(yp0, ll8) & ONE2;
                af[2] = __vcmpeq2(yp1, ll)  & ONE2;
                af[3] = __vcmpeq2(yp1, ll8) & ONE2;
                #pragma unroll
                for (int nt = 0; nt < 8; nt++)
                    mma16816(acc[mt][nt], af, bf[nt]);
            }
        }
    }

    // flush partial sums
    #pragma unroll
    for (int mt = 0; mt < 2; mt++) {
        #pragma unroll
        for (int h = 0; h < 2; h++) {
            int l = wm*32 + mt*16 + h*8 + lr4;
            if (l < NL) {
                #pragma unroll
                for (int nt = 0; nt < 8; nt++) {
                    int f = n0 + wn*64 + nt*8 + 2*lq;
                    float* dst = &g_sums[((size_t)e*NL + l)*NF + f];
                    atomicAdd(dst,     acc[mt][nt][h*2 + 0]);
                    atomicAdd(dst + 1, acc[mt][nt][h*2 + 1]);
                }
            }
        }
    }
}

// ---------------- label aggregation + final output ----------------
__global__ void combine_kernel(float* __restrict__ out) {
    const int tid = threadIdx.x;
    float pl_sel = 0.f, sel = 0.f;
    if (tid < NL) {
        float nvis = 0.f, vv = 0.f;
        #pragma unroll
        for (int e = 0; e < NE; e++) {
            float vis = g_visit[e*NL + tid];
            nvis += vis;
            vv   += g_var[e*NL + tid] * vis;
        }
        float per = vv / fmaxf(nvis, 1.0f);
        sel    = (nvis > 1.5f) ? 1.f : 0.f;
        pl_sel = per * sel;
    }
    __shared__ float s1[128], s2[128];
    s1[tid] = pl_sel; s2[tid] = sel;
    __syncthreads();
    for (int o = 64; o > 0; o >>= 1) {
        if (tid < o) { s1[tid] += s1[tid+o]; s2[tid] += s2[tid+o]; }
        __syncthreads();
    }
    if (tid == 0) {
        float mean_loss = LAM * s1[0] / fmaxf(s2[0], 1.0f);
        out[0] = mean_loss + (float)(g_ce / (double)NEB);
    }
}

// ---------------- launch ----------------
extern "C" void kernel_launch(void* const* d_in, const int* in_sizes, int n_in,
                              void* d_out, int out_size) {
    const float* feats = (const float*)d_in[0];
    const int*   y     = (const int*)  d_in[1];
    const float* W     = (const float*)d_in[2];
    const float* b     = (const float*)d_in[3];
    float* out = (float*)d_out;

    cudaFuncSetAttribute(gemm_ce_tc_kernel, cudaFuncAttributeMaxDynamicSharedMemorySize, CE_SMEM);
    cudaFuncSetAttribute(sums_gemm_kernel,  cudaFuncAttributeMaxDynamicSharedMemorySize, SU_SMEM);

    zero_kernel    <<<256, 256>>>();
    prep_wb_kernel <<<(128*NF + 255)/256, 256>>>(W);
    count_kernel   <<<(NEB + 255)/256, 256>>>(y);
    gemm_ce_tc_kernel<<<NEB/128, 256, CE_SMEM>>>(feats, y, b);
    sums_gemm_kernel <<<dim3(16, NE, 4), 256, SU_SMEM>>>(feats, y);
    var_kernel     <<<NE*NL, 256>>>();
    combine_kernel <<<1, 128>>>(out);
}

// round 5
// speedup vs baseline: 3.3942x; 1.1640x over previous
#include <cuda_runtime.h>
#include <cuda_bf16.h>
#include <math.h>
#include <stdint.h>

#define NE 4
#define NB 8192
#define NF 2048
#define NL 100
#define NEB (NE*NB)
#define LAM 1.0f

// ---------------- device scratch (no allocations allowed) ----------------
__device__ float  g_sums[NE*NL*NF];
__device__ float  g_counts[NE*NL];
__device__ float  g_var[NE*NL];
__device__ float  g_visit[NE*NL];
__device__ double g_ce;
__device__ __align__(16) __nv_bfloat16 g_Wb[128*NF];   // W^T bf16 [n][k], n>=100 zero

// ======================= PTX helpers (sm_80-compatible) ==================
__device__ __forceinline__ uint32_t smem_u32(const void* p) {
    return (uint32_t)__cvta_generic_to_shared(p);
}
__device__ __forceinline__ uint32_t swz128(uint32_t off) {   // 128B-row swizzle
    return off ^ ((off >> 3) & 0x70u);
}
__device__ __forceinline__ uint32_t swz256(uint32_t off) {   // 256B-row swizzle
    return off ^ ((off >> 4) & 0xF0u);
}
__device__ __forceinline__ void cp16(uint32_t dst, const void* src) {
    asm volatile("cp.async.cg.shared.global [%0], [%1], 16;" :: "r"(dst), "l"(src));
}
__device__ __forceinline__ void cp_commit() {
    asm volatile("cp.async.commit_group;" ::: "memory");
}
__device__ __forceinline__ void cp_wait1() {
    asm volatile("cp.async.wait_group 1;" ::: "memory");
}
__device__ __forceinline__ void cp_wait0() {
    asm volatile("cp.async.wait_group 0;" ::: "memory");
}
__device__ __forceinline__ void ldm_x4(uint32_t* r, uint32_t a) {
    asm volatile("ldmatrix.sync.aligned.m8n8.x4.shared.b16 {%0,%1,%2,%3}, [%4];"
                 : "=r"(r[0]), "=r"(r[1]), "=r"(r[2]), "=r"(r[3]) : "r"(a));
}
__device__ __forceinline__ void ldm_x2(uint32_t* r, uint32_t a) {
    asm volatile("ldmatrix.sync.aligned.m8n8.x2.shared.b16 {%0,%1}, [%2];"
                 : "=r"(r[0]), "=r"(r[1]) : "r"(a));
}
__device__ __forceinline__ void ldm_x2t(uint32_t* r, uint32_t a) {
    asm volatile("ldmatrix.sync.aligned.m8n8.x2.trans.shared.b16 {%0,%1}, [%2];"
                 : "=r"(r[0]), "=r"(r[1]) : "r"(a));
}
__device__ __forceinline__ void mma16816(float* c, const uint32_t* a, const uint32_t* b) {
    asm volatile(
        "mma.sync.aligned.m16n8k16.row.col.f32.bf16.bf16.f32 "
        "{%0,%1,%2,%3}, {%4,%5,%6,%7}, {%8,%9}, {%0,%1,%2,%3};"
        : "+f"(c[0]), "+f"(c[1]), "+f"(c[2]), "+f"(c[3])
        : "r"(a[0]), "r"(a[1]), "r"(a[2]), "r"(a[3]), "r"(b[0]), "r"(b[1]));
}
__device__ __forceinline__ uint2 cvt_f4_bf16x4(float4 v) {
    __nv_bfloat162 lo = __float22bfloat162_rn(make_float2(v.x, v.y));
    __nv_bfloat162 hi = __float22bfloat162_rn(make_float2(v.z, v.w));
    return make_uint2(*(uint32_t*)&lo, *(uint32_t*)&hi);
}

#define NCHUNK (NF/64)   // 32
#define CE_SMEM (1024 + 2*16384 + 3*16384)  // 82944
#define SCHUNK 32
#define ONE2 0x3F803F80u

// ================= setup: zero scratch + prep W^T bf16 ===================
// grid = 1281: [0,1024) prep_wb, [1024,1280) zero g_sums, 1280 small zeroes
__global__ void setup_kernel(const float* __restrict__ W) {
    const int bx = blockIdx.x, tid = threadIdx.x;
    if (bx < 1024) {
        int i = bx*256 + tid;          // 0..262143
        int n = i >> 11;
        int k = i & (NF-1);
        float v = (n < NL) ? W[(size_t)k*NL + n] : 0.f;
        g_Wb[i] = __float2bfloat16(v);
    } else if (bx < 1280) {
        int base = (bx - 1024)*256 + tid;
        for (int i = base; i < NE*NL*NF; i += 256*256)
            g_sums[i] = 0.f;
    } else {
        if (tid < NE*NL) g_counts[tid] = 0.f;
        if (tid == 0)    g_ce = 0.0;
    }
}

// ================= fat kernel: CE GEMM + sums GEMM + counts ==============
// grid = 640:
//   bx in [0,512): even -> CE tile (bx>>1), odd -> sums tile (bx>>1)
//   bx in [512,640): label counts
__global__ void __launch_bounds__(256, 2)
fat_kernel(const float* __restrict__ feats,
           const int*   __restrict__ y,
           const float* __restrict__ b) {
    const int bx  = blockIdx.x;
    const int tid = threadIdx.x;

    // ------------------------- counts tail -------------------------------
    if (bx >= 512) {
        int i = (bx - 512)*256 + tid;
        if (i < NEB) {
            int e = i / NB;
            atomicAdd(&g_counts[e*NL + y[i]], 1.0f);
        }
        return;
    }

    extern __shared__ char smx[];
    const uint32_t tile0 = (smem_u32(smx) + 1023u) & ~1023u;
    const int wid  = tid >> 5;
    const int lane = tid & 31;
    const int lq   = lane & 3;
    const int lr4  = lane >> 2;
    const float4* fv = (const float4*)feats;

    if ((bx & 1) == 0) {
        // =============== CE GEMM [32768,2048]x[2048,128pad] ===============
        const uint32_t tA[2] = { tile0, tile0 + 16384 };
        const uint32_t tB[3] = { tile0 + 32768, tile0 + 49152, tile0 + 65536 };

        __shared__ float bias_s[128];
        __shared__ float smax2[2][128];
        __shared__ float sown[2][128];
        __shared__ float sexp[2][128];
        __shared__ float redw[8];

        const int wm = wid >> 1;
        const int wn = wid & 1;
        const int m0 = (bx >> 1) * 128;

        if (tid < 128) bias_s[tid] = (tid < NL) ? b[tid] : 0.f;

        float acc[2][8][4];
        #pragma unroll
        for (int mt = 0; mt < 2; mt++)
            #pragma unroll
            for (int nt = 0; nt < 8; nt++)
                #pragma unroll
                for (int j = 0; j < 4; j++) acc[mt][nt][j] = 0.f;

        uint2 st[8];
        auto load_regs = [&](int kt) {
            #pragma unroll
            for (int i = 0; i < 8; i++) {
                int idx = i*256 + tid;
                int row = idx >> 4, q = idx & 15;
                st[i] = cvt_f4_bf16x4(fv[(size_t)(m0 + row)*(NF/4) + kt*16 + q]);
            }
        };
        auto sts_regs = [&](int s) {
            #pragma unroll
            for (int i = 0; i < 8; i++) {
                int idx = i*256 + tid;
                int row = idx >> 4, q = idx & 15;
                asm volatile("st.shared.v2.u32 [%0], {%1, %2};"
                             :: "r"(tA[s] + swz128((uint32_t)(row*128 + q*8))),
                                "r"(st[i].x), "r"(st[i].y) : "memory");
            }
        };
        auto issueB = [&](int kt, int stg) {
            #pragma unroll
            for (int i = 0; i < 4; i++) {
                int idx = i*256 + tid;
                int n = idx >> 3, q = idx & 7;
                cp16(tB[stg] + swz128((uint32_t)(n*128 + q*16)),
                     g_Wb + (size_t)n*NF + kt*64 + q*8);
            }
            cp_commit();
        };

        load_regs(0);
        issueB(0, 0);
        issueB(1, 1);

        for (int kt = 0; kt < NCHUNK; kt++) {
            const int sa = kt & 1;
            const int sb = kt % 3;
            sts_regs(sa);
            if (kt + 1 < NCHUNK) load_regs(kt + 1);
            if (kt + 1 < NCHUNK) cp_wait1(); else cp_wait0();
            __syncthreads();
            if (kt + 2 < NCHUNK) issueB(kt + 2, (kt + 2) % 3);

            #pragma unroll
            for (int k16 = 0; k16 < 4; k16++) {
                uint32_t bf[8][2];
                {
                    int l = lane & 15;
                    uint32_t boff = (uint32_t)(k16*32 + (l >> 3)*16);
                    #pragma unroll
                    for (int nt = 0; nt < 8; nt++) {
                        int n0 = wn*64 + nt*8;
                        ldm_x2(bf[nt], tB[sb] + swz128((uint32_t)((n0 + (l & 7))*128) + boff));
                    }
                }
                #pragma unroll
                for (int mt = 0; mt < 2; mt++) {
                    uint32_t af[4];
                    uint32_t aoff = (uint32_t)(k16*32 + (lane >> 4)*16);
                    ldm_x4(af, tA[sa] + swz128((uint32_t)((wm*32 + mt*16 + (lane & 15))*128) + aoff));
                    #pragma unroll
                    for (int nt = 0; nt < 8; nt++)
                        mma16816(acc[mt][nt], af, bf[nt]);
                }
            }
        }
        __syncthreads();

        // -------- fused CE epilogue --------
        #pragma unroll
        for (int mt = 0; mt < 2; mt++) {
            #pragma unroll
            for (int h = 0; h < 2; h++) {
                int lrow = wm*32 + mt*16 + h*8 + lr4;
                int yv = y[m0 + lrow];
                float mx = -1e30f, own = 0.f;
                #pragma unroll
                for (int nt = 0; nt < 8; nt++) {
                    #pragma unroll
                    for (int j = 0; j < 2; j++) {
                        int gc = wn*64 + nt*8 + 2*lq + j;
                        float v = acc[mt][nt][h*2 + j] + bias_s[gc];
                        if (gc >= NL) v = -1e30f;
                        mx = fmaxf(mx, v);
                        if (gc == yv) own = v;
                    }
                }
                mx = fmaxf(mx, __shfl_xor_sync(0xffffffffu, mx, 1));
                mx = fmaxf(mx, __shfl_xor_sync(0xffffffffu, mx, 2));
                own += __shfl_xor_sync(0xffffffffu, own, 1);
                own += __shfl_xor_sync(0xffffffffu, own, 2);
                if (lq == 0) { smax2[wn][lrow] = mx; sown[wn][lrow] = own; }
            }
        }
        __syncthreads();

        #pragma unroll
        for (int mt = 0; mt < 2; mt++) {
            #pragma unroll
            for (int h = 0; h < 2; h++) {
                int lrow = wm*32 + mt*16 + h*8 + lr4;
                float mxc = fmaxf(smax2[0][lrow], smax2[1][lrow]);
                float se = 0.f;
                #pragma unroll
                for (int nt = 0; nt < 8; nt++) {
                    #pragma unroll
                    for (int j = 0; j < 2; j++) {
                        int gc = wn*64 + nt*8 + 2*lq + j;
                        float v = acc[mt][nt][h*2 + j] + bias_s[gc];
                        if (gc < NL) se += __expf(v - mxc);
                    }
                }
                se += __shfl_xor_sync(0xffffffffu, se, 1);
                se += __shfl_xor_sync(0xffffffffu, se, 2);
                if (lq == 0) sexp[wn][lrow] = se;
            }
        }
        __syncthreads();

        float ce = 0.f;
        if (tid < 128) {
            float mxc = fmaxf(smax2[0][tid], smax2[1][tid]);
            float se  = sexp[0][tid] + sexp[1][tid];
            float own = sown[0][tid] + sown[1][tid];
            ce = mxc + __logf(se) - own;
        }
        #pragma unroll
        for (int o = 16; o > 0; o >>= 1)
            ce += __shfl_xor_sync(0xffffffffu, ce, o);
        if (lane == 0) redw[wid] = ce;
        __syncthreads();
        if (tid == 0) {
            float t = redw[0] + redw[1] + redw[2] + redw[3];
            atomicAdd(&g_ce, (double)t);
        }
    } else {
        // ====== sums GEMM: sums[e] = onehot(y[e])^T [L,B] @ feats[e] ======
        const uint32_t tF[2] = { tile0, tile0 + 16384 };
        uint32_t* sy16 = (uint32_t*)(smx + (tile0 - smem_u32(smx)) + 32768);

        const int blk = bx >> 1;            // 0..255
        const int n0  = (blk & 15) * 128;
        const int e   = (blk >> 4) & 3;
        const int bz  = (blk >> 6) * 2048;
        const int wm  = wid >> 1;
        const int wn  = wid & 1;

        {
            const int* yp = y + e*NB + bz;
            for (int j = tid; j < 1024; j += 256)
                sy16[j] = (uint32_t)yp[2*j] | ((uint32_t)yp[2*j + 1] << 16);
        }

        float acc[2][8][4];
        #pragma unroll
        for (int mt = 0; mt < 2; mt++)
            #pragma unroll
            for (int nt = 0; nt < 8; nt++)
                #pragma unroll
                for (int j = 0; j < 4; j++) acc[mt][nt][j] = 0.f;

        uint2 st[8];
        auto load_regs = [&](int kt) {
            #pragma unroll
            for (int i = 0; i < 8; i++) {
                int idx = i*256 + tid;
                int row = idx >> 5, q = idx & 31;
                st[i] = cvt_f4_bf16x4(
                    fv[(size_t)(e*NB + bz + kt*64 + row)*(NF/4) + (n0 >> 2) + q]);
            }
        };
        auto sts_regs = [&](int s) {
            #pragma unroll
            for (int i = 0; i < 8; i++) {
                int idx = i*256 + tid;
                int row = idx >> 5, q = idx & 31;
                asm volatile("st.shared.v2.u32 [%0], {%1, %2};"
                             :: "r"(tF[s] + swz256((uint32_t)(row*256 + q*8))),
                                "r"(st[i].x), "r"(st[i].y) : "memory");
            }
        };

        load_regs(0);

        for (int kt = 0; kt < SCHUNK; kt++) {
            const int s = kt & 1;
            sts_regs(s);
            if (kt + 1 < SCHUNK) load_regs(kt + 1);
            __syncthreads();

            #pragma unroll
            for (int k16 = 0; k16 < 4; k16++) {
                uint32_t bfr[8][2];
                {
                    int rr = k16*16 + (lane & 15);
                    #pragma unroll
                    for (int nt = 0; nt < 8; nt++) {
                        uint32_t cn = (uint32_t)(wn*8 + nt);
                        ldm_x2t(bfr[nt], tF[s] + swz256((uint32_t)(rr*256) + cn*16));
                    }
                }
                uint32_t yp0 = sy16[kt*32 + k16*8 + lq];
                uint32_t yp1 = sy16[kt*32 + k16*8 + 4 + lq];
                #pragma unroll
                for (int mt = 0; mt < 2; mt++) {
                    int lm = wm*32 + mt*16 + lr4;
                    uint32_t ll  = (uint32_t)lm | ((uint32_t)lm << 16);
                    uint32_t ll8 = ll + 0x00080008u;
                    uint32_t af[4];
                    af[0] = __vcmpeq2(yp0, ll)  & ONE2;
                    af[1] = __vcmpeq2(yp0, ll8) & ONE2;
                    af[2] = __vcmpeq2(yp1, ll)  & ONE2;
                    af[3] = __vcmpeq2(yp1, ll8) & ONE2;
                    #pragma unroll
                    for (int nt = 0; nt < 8; nt++)
                        mma16816(acc[mt][nt], af, bfr[nt]);
                }
            }
        }

        #pragma unroll
        for (int mt = 0; mt < 2; mt++) {
            #pragma unroll
            for (int h = 0; h < 2; h++) {
                int l = wm*32 + mt*16 + h*8 + lr4;
                if (l < NL) {
                    #pragma unroll
                    for (int nt = 0; nt < 8; nt++) {
                        int f = n0 + wn*64 + nt*8 + 2*lq;
                        float* dst = &g_sums[((size_t)e*NL + l)*NF + f];
                        atomicAdd(dst,     acc[mt][nt][h*2 + 0]);
                        atomicAdd(dst + 1, acc[mt][nt][h*2 + 1]);
                    }
                }
            }
        }
    }
}

// ---------------- per-(env,label) variance over features ----------------
__global__ void var_kernel() {
    const int el = blockIdx.x;
    float cnt = g_counts[el];
    float inv = 1.0f / fmaxf(cnt, 1.0f);
    const float* s = g_sums + (size_t)el * NF;

    float sum = 0.f, sq = 0.f;
    for (int f = threadIdx.x; f < NF; f += 256) {
        float m = s[f] * inv;
        sum += m;
        sq  = fmaf(m, m, sq);
    }
    __shared__ float s1[256], s2[256];
    s1[threadIdx.x] = sum; s2[threadIdx.x] = sq;
    __syncthreads();
    for (int o = 128; o > 0; o >>= 1) {
        if (threadIdx.x < o) { s1[threadIdx.x] += s1[threadIdx.x+o];
                               s2[threadIdx.x] += s2[threadIdx.x+o]; }
        __syncthreads();
    }
    if (threadIdx.x == 0) {
        float S = s1[0], Q = s2[0];
        float mu = S / (float)NF;
        g_var[el]   = (Q - S*mu) / (float)(NF - 1);
        g_visit[el] = (cnt > 0.f) ? 1.f : 0.f;
    }
}

// ---------------- label aggregation + final output ----------------
__global__ void combine_kernel(float* __restrict__ out) {
    const int tid = threadIdx.x;
    float pl_sel = 0.f, sel = 0.f;
    if (tid < NL) {
        float nvis = 0.f, vv = 0.f;
        #pragma unroll
        for (int e = 0; e < NE; e++) {
            float vis = g_visit[e*NL + tid];
            nvis += vis;
            vv   += g_var[e*NL + tid] * vis;
        }
        float per = vv / fmaxf(nvis, 1.0f);
        sel    = (nvis > 1.5f) ? 1.f : 0.f;
        pl_sel = per * sel;
    }
    __shared__ float s1[128], s2[128];
    s1[tid] = pl_sel; s2[tid] = sel;
    __syncthreads();
    for (int o = 64; o > 0; o >>= 1) {
        if (tid < o) { s1[tid] += s1[tid+o]; s2[tid] += s2[tid+o]; }
        __syncthreads();
    }
    if (tid == 0) {
        float mean_loss = LAM * s1[0] / fmaxf(s2[0], 1.0f);
        out[0] = mean_loss + (float)(g_ce / (double)NEB);
    }
}

// ---------------- launch ----------------
extern "C" void kernel_launch(void* const* d_in, const int* in_sizes, int n_in,
                              void* d_out, int out_size) {
    const float* feats = (const float*)d_in[0];
    const int*   y     = (const int*)  d_in[1];
    const float* W     = (const float*)d_in[2];
    const float* b     = (const float*)d_in[3];
    float* out = (float*)d_out;

    cudaFuncSetAttribute(fat_kernel, cudaFuncAttributeMaxDynamicSharedMemorySize, CE_SMEM);

    setup_kernel  <<<1281, 256>>>(W);
    fat_kernel    <<<640, 256, CE_SMEM>>>(feats, y, b);
    var_kernel    <<<NE*NL, 256>>>();
    combine_kernel<<<1, 128>>>(out);
}

// round 6
// speedup vs baseline: 3.4942x; 1.0294x over previous
#include <cuda_runtime.h>
#include <cuda_bf16.h>
#include <math.h>
#include <stdint.h>

#define NE 4
#define NB 8192
#define NF 2048
#define NL 100
#define NEB (NE*NB)
#define LAM 1.0f

// ---------------- device scratch (no allocations allowed) ----------------
__device__ float  g_sums[NE*NL*NF];
__device__ float  g_counts[NE*NL];
__device__ float  g_var[NE*NL];
__device__ float  g_visit[NE*NL];
__device__ double g_ce;
__device__ unsigned g_done;
__device__ __align__(16) __nv_bfloat16 g_Wb[128*NF];   // W^T bf16 [n][k], n>=100 zero

// ======================= PTX helpers (sm_80-compatible) ==================
__device__ __forceinline__ uint32_t smem_u32(const void* p) {
    return (uint32_t)__cvta_generic_to_shared(p);
}
__device__ __forceinline__ uint32_t swz128(uint32_t off) {   // 128B-row swizzle
    return off ^ ((off >> 3) & 0x70u);
}
__device__ __forceinline__ uint32_t swz256(uint32_t off) {   // 256B-row swizzle
    return off ^ ((off >> 4) & 0xF0u);
}
__device__ __forceinline__ void cp16(uint32_t dst, const void* src) {
    asm volatile("cp.async.cg.shared.global [%0], [%1], 16;" :: "r"(dst), "l"(src));
}
__device__ __forceinline__ void cp_commit() {
    asm volatile("cp.async.commit_group;" ::: "memory");
}
__device__ __forceinline__ void cp_wait1() {
    asm volatile("cp.async.wait_group 1;" ::: "memory");
}
__device__ __forceinline__ void cp_wait0() {
    asm volatile("cp.async.wait_group 0;" ::: "memory");
}
__device__ __forceinline__ void ldm_x4(uint32_t* r, uint32_t a) {
    asm volatile("ldmatrix.sync.aligned.m8n8.x4.shared.b16 {%0,%1,%2,%3}, [%4];"
                 : "=r"(r[0]), "=r"(r[1]), "=r"(r[2]), "=r"(r[3]) : "r"(a));
}
__device__ __forceinline__ void ldm_x2t(uint32_t* r, uint32_t a) {
    asm volatile("ldmatrix.sync.aligned.m8n8.x2.trans.shared.b16 {%0,%1}, [%2];"
                 : "=r"(r[0]), "=r"(r[1]) : "r"(a));
}
__device__ __forceinline__ void mma16816(float* c, const uint32_t* a, const uint32_t* b) {
    asm volatile(
        "mma.sync.aligned.m16n8k16.row.col.f32.bf16.bf16.f32 "
        "{%0,%1,%2,%3}, {%4,%5,%6,%7}, {%8,%9}, {%0,%1,%2,%3};"
        : "+f"(c[0]), "+f"(c[1]), "+f"(c[2]), "+f"(c[3])
        : "r"(a[0]), "r"(a[1]), "r"(a[2]), "r"(a[3]), "r"(b[0]), "r"(b[1]));
}
__device__ __forceinline__ uint2 cvt_f4_bf16x4(float4 v) {
    __nv_bfloat162 lo = __float22bfloat162_rn(make_float2(v.x, v.y));
    __nv_bfloat162 hi = __float22bfloat162_rn(make_float2(v.z, v.w));
    return make_uint2(*(uint32_t*)&lo, *(uint32_t*)&hi);
}
__device__ __forceinline__ uint32_t cvt2(float2 v) {
    __nv_bfloat162 t = __float22bfloat162_rn(v);
    return *(uint32_t*)&t;
}

#define NCHUNK (NF/64)   // 32
#define SCHUNK 32
#define ONE2 0x3F803F80u
#define FAT_SMEM (1024 + 3*16384 + 4096)   // 53248 covers CE (49KB) + sums (37KB)

// ================= setup: zero scratch + prep W^T bf16 ===================
__global__ void setup_kernel(const float* __restrict__ W) {
    const int bx = blockIdx.x, tid = threadIdx.x;
    if (bx < 1024) {
        int i = bx*256 + tid;
        int n = i >> 11;
        int k = i & (NF-1);
        float v = (n < NL) ? W[(size_t)k*NL + n] : 0.f;
        g_Wb[i] = __float2bfloat16(v);
    } else if (bx < 1280) {
        int base = (bx - 1024)*256 + tid;
        for (int i = base; i < NE*NL*NF; i += 256*256)
            g_sums[i] = 0.f;
    } else {
        if (tid < NE*NL) g_counts[tid] = 0.f;
        if (tid == 0) { g_ce = 0.0; g_done = 0u; }
    }
}

// ================= fat kernel: CE GEMM + sums GEMM + counts ==============
// grid = 640: bx<512: even->CE tile, odd->sums tile; bx>=512: counts.
__global__ void __launch_bounds__(256, 2)
fat_kernel(const float* __restrict__ feats,
           const int*   __restrict__ y,
           const float* __restrict__ b) {
    const int bx  = blockIdx.x;
    const int tid = threadIdx.x;

    if (bx >= 512) {                      // ---- counts tail ----
        int i = (bx - 512)*256 + tid;
        if (i < NEB) {
            int e = i / NB;
            atomicAdd(&g_counts[e*NL + y[i]], 1.0f);
        }
        return;
    }

    extern __shared__ char smx[];
    const uint32_t tile0 = (smem_u32(smx) + 1023u) & ~1023u;
    const int wid  = tid >> 5;
    const int lane = tid & 31;
    const int lq   = lane & 3;
    const int lr4  = lane >> 2;
    const float4* fv = (const float4*)feats;

    if ((bx & 1) == 0) {
        // ========== CE GEMM: warp = 16-row band x full 128 cols ==========
        const uint32_t tB[3] = { tile0, tile0 + 16384, tile0 + 32768 };
        __shared__ float bias_s[128];
        __shared__ float redw[8];

        const int m0 = (bx >> 1) * 128;
        if (tid < 128) bias_s[tid] = (tid < NL) ? b[tid] : 0.f;

        float acc[16][4];
        #pragma unroll
        for (int nt = 0; nt < 16; nt++)
            #pragma unroll
            for (int j = 0; j < 4; j++) acc[nt][j] = 0.f;

        // A: direct-from-global per warp. rows band*16+lr4 (+8)
        const float* aptr0 = feats + (size_t)(m0 + wid*16 + lr4) * NF + 2*lq;
        const float* aptr1 = aptr0 + 8*(size_t)NF;
        float2 sa[16];   // staging: j=0..7 -> sa[2j]=row0, sa[2j+1]=row1

        auto loadA = [&](int kt, int jlo, int jhi) {
            #pragma unroll
            for (int j = jlo; j < jhi; j++) {
                sa[2*j]   = *(const float2*)(aptr0 + kt*64 + 8*j);
                sa[2*j+1] = *(const float2*)(aptr1 + kt*64 + 8*j);
            }
        };
        auto issueB = [&](int kt, int stg) {
            #pragma unroll
            for (int i = 0; i < 4; i++) {
                int idx = i*256 + tid;
                int n = idx >> 3, q = idx & 7;
                cp16(tB[stg] + swz128((uint32_t)(n*128 + q*16)),
                     g_Wb + (size_t)n*NF + kt*64 + q*8);
            }
            cp_commit();
        };

        // B ldmatrix address (x4 -> two consecutive n-tiles, full k16)
        const int l7    = lane & 7;
        const int khalf = (lane >> 3) & 1;
        const int npair = (lane >> 4) & 1;

        issueB(0, 0);
        issueB(1, 1);
        loadA(0, 0, 8);

        for (int kt = 0; kt < NCHUNK; kt++) {
            const int sb = kt % 3;
            if (kt + 1 < NCHUNK) cp_wait1(); else cp_wait0();
            __syncthreads();
            if (kt + 2 < NCHUNK) issueB(kt + 2, (kt + 2) % 3);
            const bool more = (kt + 1 < NCHUNK);

            #pragma unroll
            for (int s = 0; s < 4; s++) {
                uint32_t af[4];
                af[0] = cvt2(sa[4*s + 0]);
                af[1] = cvt2(sa[4*s + 1]);
                af[2] = cvt2(sa[4*s + 2]);
                af[3] = cvt2(sa[4*s + 3]);
                uint32_t bf[16][2];
                #pragma unroll
                for (int nt = 0; nt < 16; nt += 2) {
                    uint32_t row = (uint32_t)(nt*8 + npair*8 + l7);
                    uint32_t boff = (uint32_t)(s*32 + khalf*16);
                    uint32_t r4[4];
                    ldm_x4(r4, tB[sb] + swz128(row*128 + boff));
                    bf[nt][0] = r4[0]; bf[nt][1] = r4[1];
                    bf[nt+1][0] = r4[2]; bf[nt+1][1] = r4[3];
                }
                if (s == 1 && more) loadA(kt + 1, 0, 4);
                #pragma unroll
                for (int nt = 0; nt < 16; nt++)
                    mma16816(acc[nt], af, bf[nt]);
                if (s == 3 && more) loadA(kt + 1, 4, 8);
            }
        }

        // -------- warp-local CE epilogue --------
        float ce = 0.f;
        #pragma unroll
        for (int h = 0; h < 2; h++) {
            int row = m0 + wid*16 + h*8 + lr4;
            int yv = y[row];
            float mx = -1e30f, own = 0.f;
            #pragma unroll
            for (int nt = 0; nt < 16; nt++) {
                #pragma unroll
                for (int j = 0; j < 2; j++) {
                    int gc = nt*8 + 2*lq + j;
                    float v = acc[nt][h*2 + j] + bias_s[gc];
                    if (gc >= NL) v = -1e30f;
                    mx = fmaxf(mx, v);
                    if (gc == yv) own = v;
                }
            }
            mx = fmaxf(mx, __shfl_xor_sync(0xffffffffu, mx, 1));
            mx = fmaxf(mx, __shfl_xor_sync(0xffffffffu, mx, 2));
            own += __shfl_xor_sync(0xffffffffu, own, 1);
            own += __shfl_xor_sync(0xffffffffu, own, 2);
            float se = 0.f;
            #pragma unroll
            for (int nt = 0; nt < 16; nt++) {
                #pragma unroll
                for (int j = 0; j < 2; j++) {
                    int gc = nt*8 + 2*lq + j;
                    float v = acc[nt][h*2 + j] + bias_s[gc];
                    if (gc < NL) se += __expf(v - mx);
                }
            }
            se += __shfl_xor_sync(0xffffffffu, se, 1);
            se += __shfl_xor_sync(0xffffffffu, se, 2);
            if (lq == 0) ce += mx + __logf(se) - own;
        }
        #pragma unroll
        for (int o = 16; o > 0; o >>= 1)
            ce += __shfl_xor_sync(0xffffffffu, ce, o);
        if (lane == 0) redw[wid] = ce;
        __syncthreads();
        if (tid == 0) {
            float t = 0.f;
            #pragma unroll
            for (int w = 0; w < 8; w++) t += redw[w];
            atomicAdd(&g_ce, (double)t);
        }
    } else {
        // ====== sums GEMM: sums[e] = onehot(y[e])^T [L,B] @ feats[e] ======
        const uint32_t tF[2] = { tile0, tile0 + 16384 };
        uint32_t* sy16 = (uint32_t*)(smx + (tile0 - smem_u32(smx)) + 32768);

        const int blk = bx >> 1;
        const int n0  = (blk & 15) * 128;
        const int e   = (blk >> 4) & 3;
        const int bz  = (blk >> 6) * 2048;
        const int wm  = wid >> 1;
        const int wn  = wid & 1;

        {
            const int* yp = y + e*NB + bz;
            for (int j = tid; j < 1024; j += 256)
                sy16[j] = (uint32_t)yp[2*j] | ((uint32_t)yp[2*j + 1] << 16);
        }

        float acc[2][8][4];
        #pragma unroll
        for (int mt = 0; mt < 2; mt++)
            #pragma unroll
            for (int nt = 0; nt < 8; nt++)
                #pragma unroll
                for (int j = 0; j < 4; j++) acc[mt][nt][j] = 0.f;

        uint2 st[8];
        auto load_regs = [&](int kt) {
            #pragma unroll
            for (int i = 0; i < 8; i++) {
                int idx = i*256 + tid;
                int row = idx >> 5, q = idx & 31;
                st[i] = cvt_f4_bf16x4(
                    fv[(size_t)(e*NB + bz + kt*64 + row)*(NF/4) + (n0 >> 2) + q]);
            }
        };
        auto sts_regs = [&](int s) {
            #pragma unroll
            for (int i = 0; i < 8; i++) {
                int idx = i*256 + tid;
                int row = idx >> 5, q = idx & 31;
                asm volatile("st.shared.v2.u32 [%0], {%1, %2};"
                             :: "r"(tF[s] + swz256((uint32_t)(row*256 + q*8))),
                                "r"(st[i].x), "r"(st[i].y) : "memory");
            }
        };

        load_regs(0);

        for (int kt = 0; kt < SCHUNK; kt++) {
            const int s = kt & 1;
            sts_regs(s);
            if (kt + 1 < SCHUNK) load_regs(kt + 1);
            __syncthreads();

            #pragma unroll
            for (int k16 = 0; k16 < 4; k16++) {
                uint32_t bfr[8][2];
                {
                    int rr = k16*16 + (lane & 15);
                    #pragma unroll
                    for (int nt = 0; nt < 8; nt++) {
                        uint32_t cn = (uint32_t)(wn*8 + nt);
                        ldm_x2t(bfr[nt], tF[s] + swz256((uint32_t)(rr*256) + cn*16));
                    }
                }
                uint32_t yp0 = sy16[kt*32 + k16*8 + lq];
                uint32_t yp1 = sy16[kt*32 + k16*8 + 4 + lq];
                #pragma unroll
                for (int mt = 0; mt < 2; mt++) {
                    int lm = wm*32 + mt*16 + lr4;
                    uint32_t ll  = (uint32_t)lm | ((uint32_t)lm << 16);
                    uint32_t ll8 = ll + 0x00080008u;
                    uint32_t af[4];
                    af[0] = __vcmpeq2(yp0, ll)  & ONE2;
                    af[1] = __vcmpeq2(yp0, ll8) & ONE2;
                    af[2] = __vcmpeq2(yp1, ll)  & ONE2;
                    af[3] = __vcmpeq2(yp1, ll8) & ONE2;
                    #pragma unroll
                    for (int nt = 0; nt < 8; nt++)
                        mma16816(acc[mt][nt], af, bfr[nt]);
                }
            }
        }

        #pragma unroll
        for (int mt = 0; mt < 2; mt++) {
            #pragma unroll
            for (int h = 0; h < 2; h++) {
                int l = wm*32 + mt*16 + h*8 + lr4;
                if (l < NL) {
                    #pragma unroll
                    for (int nt = 0; nt < 8; nt++) {
                        int f = n0 + wn*64 + nt*8 + 2*lq;
                        float* dst = &g_sums[((size_t)e*NL + l)*NF + f];
                        atomicAdd(dst,     acc[mt][nt][h*2 + 0]);
                        atomicAdd(dst + 1, acc[mt][nt][h*2 + 1]);
                    }
                }
            }
        }
    }
}

// ======== variance per (env,label) + fused final combine ================
__global__ void var_combine_kernel(float* __restrict__ out) {
    const int el = blockIdx.x;
    const int tid = threadIdx.x;
    float cnt = g_counts[el];
    float inv = 1.0f / fmaxf(cnt, 1.0f);
    const float* s = g_sums + (size_t)el * NF;

    float sum = 0.f, sq = 0.f;
    for (int f = tid; f < NF; f += 256) {
        float m = s[f] * inv;
        sum += m;
        sq  = fmaf(m, m, sq);
    }
    __shared__ float s1[256], s2[256];
    s1[tid] = sum; s2[tid] = sq;
    __syncthreads();
    for (int o = 128; o > 0; o >>= 1) {
        if (tid < o) { s1[tid] += s1[tid+o]; s2[tid] += s2[tid+o]; }
        __syncthreads();
    }
    __shared__ bool last;
    if (tid == 0) {
        float S = s1[0], Q = s2[0];
        float mu = S / (float)NF;
        g_var[el]   = (Q - S*mu) / (float)(NF - 1);
        g_visit[el] = (cnt > 0.f) ? 1.f : 0.f;
        __threadfence();
        unsigned v = atomicAdd(&g_done, 1u);
        last = (v == (unsigned)(NE*NL - 1));
    }
    __syncthreads();
    if (!last) return;
    __threadfence();

    // ---- final combine (single surviving block) ----
    float pl_sel = 0.f, sel = 0.f;
    if (tid < NL) {
        float nvis = 0.f, vv = 0.f;
        #pragma unroll
        for (int e = 0; e < NE; e++) {
            float vis = g_visit[e*NL + tid];
            nvis += vis;
            vv   += g_var[e*NL + tid] * vis;
        }
        float per = vv / fmaxf(nvis, 1.0f);
        sel    = (nvis > 1.5f) ? 1.f : 0.f;
        pl_sel = per * sel;
    }
    __syncthreads();
    s1[tid] = pl_sel; s2[tid] = sel;
    __syncthreads();
    for (int o = 128; o > 0; o >>= 1) {
        if (tid < o) { s1[tid] += s1[tid+o]; s2[tid] += s2[tid+o]; }
        __syncthreads();
    }
    if (tid == 0) {
        float mean_loss = LAM * s1[0] / fmaxf(s2[0], 1.0f);
        out[0] = mean_loss + (float)(g_ce / (double)NEB);
    }
}

// ---------------- launch ----------------
extern "C" void kernel_launch(void* const* d_in, const int* in_sizes, int n_in,
                              void* d_out, int out_size) {
    const float* feats = (const float*)d_in[0];
    const int*   y     = (const int*)  d_in[1];
    const float* W     = (const float*)d_in[2];
    const float* b     = (const float*)d_in[3];
    float* out = (float*)d_out;

    cudaFuncSetAttribute(fat_kernel, cudaFuncAttributeMaxDynamicSharedMemorySize, FAT_SMEM);

    setup_kernel      <<<1281, 256>>>(W);
    fat_kernel        <<<640, 256, FAT_SMEM>>>(feats, y, b);
    var_combine_kernel<<<NE*NL, 256>>>(out);
}